// round 15
// baseline (speedup 1.0000x reference)
#include <cuda_runtime.h>

// OrdLoss: sum over valid voxels of [k<=t]*log(clip(p)) + [k>t]*log(clip(1-p)),
// divided by -count(valid). pred [N,C,D,H,W] f32, target replicated over C
// (read channel 0 only), mask [N,1,D,H,W] i32.
//
// R15 = R13 mainloop (converged: 12.80us across 7 structural sweeps) with the
// serial tail replaced by DETERMINISTIC fixed-point atomic accumulation:
//  * each block atomicAdds llrintf(partial * 2^24) into one u64. Integer
//    addition is associative -> bit-identical result for any arrival order
//    (float atomics would not be). Quantization: <= 1024 * 2^-25 ~ 3e-5
//    absolute on a ~1e7 sum -> ~1e-12 relative.
//  * sum/count adds precede the acq_rel ticket bump (release) -> the last
//    block's acquire sees all adds; it reads 2 scalars and writes -s/S.
//    Replaces per-block release-stores + 2048 L2 latency reads + block reduce.
//  * mainloop: log2-domain accumulation (single *ln2 at end), saturate-abs
//    select elimination, mask-folded clip floor, default cache policy,
//    int32 addressing, 32 regs / 8 blocks/SM / single wave.

#define N_      2
#define C_      16
#define MSP     (32 * 128 * 128)      // 524288 voxels per batch item
#define NVOX    (N_ * MSP)            // 1048576
#define NGROUPS (NVOX / 4)            // 262144 float4 groups
#define BLOCKS  1024
#define THREADS 256
#define FPSCALE 16777216.0f           // 2^24 fixed-point scale
// BLOCKS*THREADS == NGROUPS exactly

__device__ unsigned long long g_sum = 0;   // fixed-point partial sum
__device__ unsigned int       g_cnt = 0;   // valid-voxel count
__device__ unsigned int       g_ticket = 0;

__global__ void __launch_bounds__(THREADS, 8)
ord_loss_fused(const float* __restrict__ pred,
               const int*   __restrict__ target,
               const int*   __restrict__ mask,
               float*       __restrict__ out)
{
    const int g = blockIdx.x * THREADS + threadIdx.x;  // group of 4 voxels
    const int m = g * 4;
    const int n = m >> 19;                              // MSP == 2^19
    const int base = m + n * (C_ - 1) * MSP;            // n*C*MSP + spatial

    const int4 mk = *reinterpret_cast<const int4*>(mask + m);
    const int4 tg = *reinterpret_cast<const int4*>(target + base);

    // negated float targets: bias_k = saturate(k + nt)
    const float nt0 = -(float)tg.x;
    const float nt1 = -(float)tg.y;
    const float nt2 = -(float)tg.z;
    const float nt3 = -(float)tg.w;

    // mask folded into per-voxel clip floor: invalid -> floor 1.0 -> log2 0
    const float c0 = (mk.x > 0) ? 1e-8f : 1.0f;
    const float c1 = (mk.y > 0) ? 1e-8f : 1.0f;
    const float c2 = (mk.z > 0) ? 1e-8f : 1.0f;
    const float c3 = (mk.w > 0) ? 1e-8f : 1.0f;
    int cnt = (mk.x > 0) + (mk.y > 0) + (mk.z > 0) + (mk.w > 0);

    float acc = 0.0f;                                   // log2 domain

#pragma unroll
    for (int k = 0; k < C_; ++k) {
        const float4 p = __ldg(reinterpret_cast<const float4*>(pred + base + k * MSP));
        const float kf = (float)k;                       // unrolled immediate
        // bias = 0 when k<=t, 1 when k>t; q = |bias - p| = p or 1-p (exact)
        const float q0 = fmaxf(fabsf(__saturatef(kf + nt0) - p.x), c0);
        const float q1 = fmaxf(fabsf(__saturatef(kf + nt1) - p.y), c1);
        const float q2 = fmaxf(fabsf(__saturatef(kf + nt2) - p.z), c2);
        const float q3 = fmaxf(fabsf(__saturatef(kf + nt3) - p.w), c3);
        acc += __log2f((q0 * q1) * (q2 * q3));           // product >= 1e-32
    }

    float a = acc * 0.69314718055994531f;               // log2 -> ln, once

    // ---- warp reduce ----
#pragma unroll
    for (int off = 16; off > 0; off >>= 1) {
        a   += __shfl_xor_sync(0xFFFFFFFFu, a, off);
        cnt += __shfl_xor_sync(0xFFFFFFFFu, cnt, off);
    }

    __shared__ float sa[THREADS / 32];
    __shared__ int   sc[THREADS / 32];
    __shared__ bool  s_last;
    const int wid = threadIdx.x >> 5;
    const int lid = threadIdx.x & 31;
    if (lid == 0) { sa[wid] = a; sc[wid] = cnt; }
    __syncthreads();

    if (threadIdx.x == 0) {
        float aa = sa[0] + sa[1] + sa[2] + sa[3] + sa[4] + sa[5] + sa[6] + sa[7];
        int   cc = sc[0] + sc[1] + sc[2] + sc[3] + sc[4] + sc[5] + sc[6] + sc[7];
        // deterministic fixed-point accumulation (integer add = associative)
        const long long q = llrintf(aa * FPSCALE);
        atomicAdd(&g_sum, (unsigned long long)q);
        atomicAdd(&g_cnt, (unsigned int)cc);
        // release: the two adds above are ordered before this ticket bump
        unsigned int old;
        asm volatile("atom.acq_rel.gpu.global.add.u32 %0, [%1], %2;"
                     : "=r"(old) : "l"(&g_ticket), "r"(1u) : "memory");
        s_last = (old == BLOCKS - 1);
    }
    __syncthreads();

    if (!s_last) return;

    // ---- last block: two scalar reads, write, reset ----
    if (threadIdx.x == 0) {
        unsigned long long su;
        unsigned int cc;
        asm volatile("ld.acquire.gpu.global.u64 %0, [%1];"
                     : "=l"(su) : "l"(&g_sum) : "memory");
        asm volatile("ld.acquire.gpu.global.u32 %0, [%1];"
                     : "=r"(cc) : "l"(&g_cnt) : "memory");
        const float ss = (float)(long long)su * (1.0f / FPSCALE);
        out[0] = -ss / (float)cc;
        // reset for next graph replay
        g_sum = 0ull;
        g_cnt = 0u;
        asm volatile("st.release.gpu.global.b32 [%0], %1;"
                     :: "l"(&g_ticket), "r"(0u) : "memory");
    }
}

extern "C" void kernel_launch(void* const* d_in, const int* in_sizes, int n_in,
                              void* d_out, int out_size)
{
    const float* pred   = (const float*)d_in[0];
    const int*   target = (const int*)d_in[1];
    const int*   mask   = (const int*)d_in[2];
    float*       out    = (float*)d_out;

    ord_loss_fused<<<BLOCKS, THREADS>>>(pred, target, mask, out);
}

// round 16
// speedup vs baseline: 1.0226x; 1.0226x over previous
#include <cuda_runtime.h>

// OrdLoss: sum over valid voxels of [k<=t]*log(clip(p)) + [k>t]*log(clip(1-p)),
// divided by -count(valid). pred [N,C,D,H,W] f32, target replicated over C
// (read channel 0 only), mask [N,1,D,H,W] i32.
//
// R16 = R13 (best family: 12.80us, rel_err 0) with 128-thread blocks
// (2048 blocks): finer wave ramp-down granularity (slowest-CTA overhang
// halves), cheaper epilogue syncs, still single resident wave
// (16 blocks/SM x 148 = 2368 >= 2048 at 32 regs). R15's atomic tail
// reverted (same-address L2 atomics serialized, +0.25us).
//
//  * log2-domain accumulation: acc += log2(P4), single *ln2 at the end
//    (P4 >= 1e-32, no underflow).
//  * select elimination: (k<=t)? p : 1-p == |saturate(k-t) - p| (exact).
//  * mask folded into clip floor: c_v = valid ? 1e-8 : 1.0 -> log2(1)=0.
//  * default cache policy; int32 addressing.
//  * epilogue: st.release.gpu partials + atom.acq_rel ticket (no CCTL.IVALL).

#define N_      2
#define C_      16
#define MSP     (32 * 128 * 128)      // 524288 voxels per batch item
#define NVOX    (N_ * MSP)            // 1048576
#define NGROUPS (NVOX / 4)            // 262144 float4 groups
#define BLOCKS  2048
#define THREADS 128
#define NWARP   (THREADS / 32)        // 4
// BLOCKS*THREADS == NGROUPS exactly

__device__ float g_partial[BLOCKS];
__device__ int   g_count[BLOCKS];
__device__ unsigned int g_ticket = 0;

__global__ void __launch_bounds__(THREADS, 16)
ord_loss_fused(const float* __restrict__ pred,
               const int*   __restrict__ target,
               const int*   __restrict__ mask,
               float*       __restrict__ out)
{
    const int g = blockIdx.x * THREADS + threadIdx.x;  // group of 4 voxels
    const int m = g * 4;
    const int n = m >> 19;                              // MSP == 2^19
    const int base = m + n * (C_ - 1) * MSP;            // n*C*MSP + spatial

    const int4 mk = *reinterpret_cast<const int4*>(mask + m);
    const int4 tg = *reinterpret_cast<const int4*>(target + base);

    // negated float targets: bias_k = saturate(k + nt)
    const float nt0 = -(float)tg.x;
    const float nt1 = -(float)tg.y;
    const float nt2 = -(float)tg.z;
    const float nt3 = -(float)tg.w;

    // mask folded into per-voxel clip floor: invalid -> floor 1.0 -> log2 0
    const float c0 = (mk.x > 0) ? 1e-8f : 1.0f;
    const float c1 = (mk.y > 0) ? 1e-8f : 1.0f;
    const float c2 = (mk.z > 0) ? 1e-8f : 1.0f;
    const float c3 = (mk.w > 0) ? 1e-8f : 1.0f;
    int cnt = (mk.x > 0) + (mk.y > 0) + (mk.z > 0) + (mk.w > 0);

    float acc = 0.0f;                                   // log2 domain

#pragma unroll
    for (int k = 0; k < C_; ++k) {
        const float4 p = __ldg(reinterpret_cast<const float4*>(pred + base + k * MSP));
        const float kf = (float)k;                       // unrolled immediate
        // bias = 0 when k<=t, 1 when k>t; q = |bias - p| = p or 1-p (exact)
        const float q0 = fmaxf(fabsf(__saturatef(kf + nt0) - p.x), c0);
        const float q1 = fmaxf(fabsf(__saturatef(kf + nt1) - p.y), c1);
        const float q2 = fmaxf(fabsf(__saturatef(kf + nt2) - p.z), c2);
        const float q3 = fmaxf(fabsf(__saturatef(kf + nt3) - p.w), c3);
        acc += __log2f((q0 * q1) * (q2 * q3));           // product >= 1e-32
    }

    float a = acc * 0.69314718055994531f;               // log2 -> ln, once

    // ---- warp reduce ----
#pragma unroll
    for (int off = 16; off > 0; off >>= 1) {
        a   += __shfl_xor_sync(0xFFFFFFFFu, a, off);
        cnt += __shfl_xor_sync(0xFFFFFFFFu, cnt, off);
    }

    __shared__ float sa[NWARP];
    __shared__ int   sc[NWARP];
    __shared__ bool  s_last;
    const int wid = threadIdx.x >> 5;
    const int lid = threadIdx.x & 31;
    if (lid == 0) { sa[wid] = a; sc[wid] = cnt; }
    __syncthreads();

    if (threadIdx.x == 0) {
        float aa = sa[0] + sa[1] + sa[2] + sa[3];
        int   cc = sc[0] + sc[1] + sc[2] + sc[3];
        asm volatile("st.release.gpu.global.f32 [%0], %1;"
                     :: "l"(&g_partial[blockIdx.x]), "f"(aa) : "memory");
        asm volatile("st.release.gpu.global.b32 [%0], %1;"
                     :: "l"(&g_count[blockIdx.x]), "r"(cc) : "memory");
        unsigned int old;
        asm volatile("atom.acq_rel.gpu.global.add.u32 %0, [%1], %2;"
                     : "=r"(old) : "l"(&g_ticket), "r"(1u) : "memory");
        s_last = (old == BLOCKS - 1);
    }
    __syncthreads();

    if (!s_last) return;

    // ---- last block: final reduction over 2048 partials, fixed order ----
    float s = 0.0f;
    int   c = 0;
#pragma unroll
    for (int i = 0; i < BLOCKS / THREADS; ++i) {          // 16 per thread
        const int idx = threadIdx.x + i * THREADS;
        s += __ldcg(&g_partial[idx]);
        c += __ldcg(&g_count[idx]);
    }
#pragma unroll
    for (int off = 16; off > 0; off >>= 1) {
        s += __shfl_xor_sync(0xFFFFFFFFu, s, off);
        c += __shfl_xor_sync(0xFFFFFFFFu, c, off);
    }
    __shared__ float fa[NWARP];
    __shared__ int   fc[NWARP];
    if (lid == 0) { fa[wid] = s; fc[wid] = c; }
    __syncthreads();
    if (threadIdx.x == 0) {
        float ss = fa[0] + fa[1] + fa[2] + fa[3];
        int   cc = fc[0] + fc[1] + fc[2] + fc[3];
        out[0] = -ss / (float)cc;
        g_ticket = 0;   // reset for next graph replay
    }
}

extern "C" void kernel_launch(void* const* d_in, const int* in_sizes, int n_in,
                              void* d_out, int out_size)
{
    const float* pred   = (const float*)d_in[0];
    const int*   target = (const int*)d_in[1];
    const int*   mask   = (const int*)d_in[2];
    float*       out    = (float*)d_out;

    ord_loss_fused<<<BLOCKS, THREADS>>>(pred, target, mask, out);
}